// round 5
// baseline (speedup 1.0000x reference)
#include <cuda_runtime.h>
#include <math.h>

#define Bn 4
#define Cn 2
#define Tn 8
#define Hn 128
#define Wn 128
#define Nn (Tn*Hn*Wn)        // 131072
#define Dn 512
#define Pn 32
#define Fn (Cn + 3*Pn)       // 98
#define Mn 65536

#define CHUNK 8192
#define NCHUNK (Nn/CHUNK)    // 16
#define NCOMPACT (NCHUNK*Bn) // 64 compact blocks
#define DT 128               // d-tile
#define WM 32                // consecutive m per warp
#define MT (32*WM)           // 1024 m per block (32 warps)
#define UN 4                 // record prefetch depth
#define NSM 148
#define NDG 4                // d-groups (512/128)
#define JGN (NSM/NDG)        // 37 blocks per d-group
#define SMEM_MAIN ((Tn+Hn+Wn)*DT*4)   // 135168 bytes

// scratch (no cudaMalloc allowed; zero-initialized at load)
__device__ int    g_pref[Bn*NCHUNK];   // lookback: (inclusive prefix)+1, 0 = not ready (self-resetting)
__device__ int    g_cnt[Bn];
__device__ float4 g_rec[Bn*Mn];        // {v0, v1, vi_as_float_bits, 0} for m < cnt[b]
__device__ float  g_Et[Tn*Dn];
__device__ float  g_Eh[Hn*Dn];
__device__ float  g_Ew[Wn*Dn];

// ---------------- fused: compact (blocks 0..63) + projected tables (blocks 64..327) ----------------
__global__ void __launch_bounds__(256) k_fused(const int* __restrict__ mask,
                                               const float* __restrict__ y,
                                               const float* __restrict__ pw) {
    int tid = threadIdx.x;

    if (blockIdx.x < NCOMPACT) {
        int b = blockIdx.x >> 4;
        int c = blockIdx.x & 15;
        const int4* mk = (const int4*)(mask + (size_t)b*Nn + c*CHUNK);

        int4 v[8];
        int cnt = 0;
        #pragma unroll
        for (int k = 0; k < 8; k++) {
            v[k] = mk[tid*8 + k];
            cnt += (v[k].x != 0) + (v[k].y != 0) + (v[k].z != 0) + (v[k].w != 0);
        }
        int incl = cnt;
        #pragma unroll
        for (int o = 1; o < 32; o <<= 1) {
            int n = __shfl_up_sync(0xffffffffu, incl, o);
            if ((tid & 31) >= o) incl += n;
        }
        __shared__ int wsum[8];
        __shared__ int wbase[8];
        __shared__ int sbase;
        if ((tid & 31) == 31) wsum[tid >> 5] = incl;
        __syncthreads();

        if (tid == 0) {
            int r = 0;
            #pragma unroll
            for (int i = 0; i < 8; i++) { wbase[i] = r; r += wsum[i]; }
            int total = r;
            int prev = 0;
            if (c > 0) {
                int p;
                while ((p = atomicAdd(&g_pref[b*NCHUNK + c - 1], 0)) == 0) { }
                prev = p - 1;
                atomicExch(&g_pref[b*NCHUNK + c - 1], 0);   // self-reset for next replay
            }
            int my_incl = prev + total;
            if (c == NCHUNK - 1) g_cnt[b] = (my_incl < Mn) ? my_incl : Mn;
            else                 atomicExch(&g_pref[b*NCHUNK + c], my_incl + 1);
            sbase = prev;
        }
        __syncthreads();

        int r = sbase + wbase[tid >> 5] + incl - cnt;
        int vbase = c*CHUNK + tid*32;
        const float* y0 = y + (size_t)b*Cn*Nn;
        float4* rec = g_rec + b*Mn;
        #pragma unroll
        for (int k = 0; k < 8; k++) {
            int e[4] = { v[k].x, v[k].y, v[k].z, v[k].w };
            #pragma unroll
            for (int j = 0; j < 4; j++) {
                if (e[j] != 0) {
                    if (r < Mn) {
                        int vi = vbase + k*4 + j;
                        float4 rr;
                        rr.x = __ldg(y0 + vi);
                        rr.y = __ldg(y0 + Nn + vi);
                        rr.z = __int_as_float(vi);
                        rr.w = 0.0f;
                        rec[r] = rr;
                    }
                    r++;
                }
            }
        }
    } else {
        int row = blockIdx.x - NCOMPACT;   // 0..263
        __shared__ float emb[32];
        int pos, base;
        float* tab;
        if (row < Tn)           { pos = row;           base = Cn;         tab = g_Et + pos*Dn; }
        else if (row < Tn+Hn)   { pos = row - Tn;      base = Cn + Pn;    tab = g_Eh + pos*Dn; }
        else                    { pos = row - Tn - Hn; base = Cn + 2*Pn;  tab = g_Ew + pos*Dn; }

        if (tid < 16) {
            float omega = exp2f(-(float)tid * (13.287712379549449f / 16.0f));  // 10000^(-j/16)
            float a = (float)pos * omega;
            float s, cth;
            sincosf(a, &s, &cth);
            emb[tid] = s;
            emb[tid + 16] = cth;
        }
        __syncthreads();

        for (int d = tid; d < Dn; d += 256) {
            float acc = 0.0f;
            const float* wrow = pw + d*Fn + base;
            #pragma unroll
            for (int p = 0; p < 32; p++) acc += emb[p] * wrow[p];
            tab[d] = acc;
        }
    }
}

// ---------------- main: persistent, warp-sequential m with (t,h)-row register cache ----------------
__global__ void __launch_bounds__(1024, 1) k_main(
    const float* __restrict__ pw,
    const float* __restrict__ pb,
    float* __restrict__ out)
{
    extern __shared__ float s[];
    float* sEt = s;                   // Tn*DT
    float* sEh = s + Tn*DT;           // Hn*DT
    float* sEw = s + (Tn+Hn)*DT;      // Wn*DT

    int g  = blockIdx.x & (NDG - 1);   // d-group
    int jg = blockIdx.x >> 2;          // 0..36
    int d0 = g * DT;
    int tid = threadIdx.x;
    int wid = tid >> 5;                // warp 0..31
    int col = tid & 31;                // d lane
    int dl  = col * 4;
    int d   = d0 + dl;

    // one-time table fill for this block's fixed d-tile
    for (int i = tid; i < Tn*(DT/4); i += 1024) {
        int row = i >> 5, c4 = i & 31;
        ((float4*)sEt)[i] = *(const float4*)&g_Et[row*Dn + d0 + c4*4];
    }
    for (int i = tid; i < Hn*(DT/4); i += 1024) {
        int row = i >> 5, c4 = i & 31;
        ((float4*)sEh)[i] = *(const float4*)&g_Eh[row*Dn + d0 + c4*4];
        ((float4*)sEw)[i] = *(const float4*)&g_Ew[row*Dn + d0 + c4*4];
    }

    float w0[4], w1[4], bs[4];
    #pragma unroll
    for (int k = 0; k < 4; k++) {
        w0[k] = pw[(d + k)*Fn + 0];
        w1[k] = pw[(d + k)*Fn + 1];
        bs[k] = pb[d + k];
    }
    __syncthreads();

    const int TILES = Bn * (Mn / MT);   // 256

    for (int tile = jg; tile < TILES; tile += JGN) {
        int b  = tile >> 6;                 // tile / 64
        int m0 = (tile & 63) * MT;
        int cnt = __ldg(&g_cnt[b]);

        if (g == 0) {
            int m = m0 + tid;
            out[(size_t)Bn*Mn*Dn + b*Mn + m] = (m < cnt) ? 0.0f : 1.0f;
        }

        const float4* rec = g_rec + b*Mn;
        float* ob = out + (size_t)b*Mn*Dn + d;

        int mw0 = m0 + wid*WM;              // this warp's 32 consecutive m
        int tp = -1, hp = -1;
        float4 sth = make_float4(bs[0], bs[1], bs[2], bs[3]);

        #pragma unroll 1
        for (int mo = 0; mo < WM; mo += UN) {
            float4 r[UN];
            #pragma unroll
            for (int j = 0; j < UN; j++) r[j] = __ldg(rec + mw0 + mo + j);

            #pragma unroll
            for (int j = 0; j < UN; j++) {
                int m = mw0 + mo + j;
                float4 o;
                if (m < cnt) {
                    int vi = __float_as_int(r[j].z);
                    int t = (vi >> 14) & 7;
                    int h = (vi >> 7) & 127;
                    int w = vi & 127;
                    if ((t != tp) || (h != hp)) {       // warp-uniform
                        float4 et = *(const float4*)&sEt[t*DT + dl];
                        float4 eh = *(const float4*)&sEh[h*DT + dl];
                        sth.x = bs[0] + et.x + eh.x;
                        sth.y = bs[1] + et.y + eh.y;
                        sth.z = bs[2] + et.z + eh.z;
                        sth.w = bs[3] + et.w + eh.w;
                        tp = t; hp = h;
                    }
                    float4 ew = *(const float4*)&sEw[w*DT + dl];
                    o.x = sth.x + ew.x + r[j].x*w0[0] + r[j].y*w1[0];
                    o.y = sth.y + ew.y + r[j].x*w0[1] + r[j].y*w1[1];
                    o.z = sth.z + ew.z + r[j].x*w0[2] + r[j].y*w1[2];
                    o.w = sth.w + ew.w + r[j].x*w0[3] + r[j].y*w1[3];
                } else {
                    o = make_float4(bs[0], bs[1], bs[2], bs[3]);
                }
                __stcs((float4*)&ob[(size_t)m*Dn], o);
            }
        }
    }
}

extern "C" void kernel_launch(void* const* d_in, const int* in_sizes, int n_in,
                              void* d_out, int out_size) {
    const float* y    = (const float*)d_in[0];   // y_obs  (B,C,T,H,W)
    const int*   mask = (const int*)  d_in[1];   // mask1  (B,1,T,H,W)
    const float* pw   = (const float*)d_in[2];   // proj_w (D, F)
    const float* pb   = (const float*)d_in[3];   // proj_b (D,)
    float* out = (float*)d_out;

    k_fused<<<NCOMPACT + Tn + Hn + Wn, 256>>>(mask, y, pw);   // launch 0

    static bool attr_set = false;
    if (!attr_set) {
        cudaFuncSetAttribute(k_main, cudaFuncAttributeMaxDynamicSharedMemorySize, SMEM_MAIN);
        attr_set = true;
    }
    k_main<<<NSM, 1024, SMEM_MAIN>>>(pw, pb, out);            // launch 1
}